// round 4
// baseline (speedup 1.0000x reference)
#include <cuda_runtime.h>
#include <math.h>
#include <stdint.h>

#define BATCH 4
#define SEQ   1024
#define DM    768
#define NH    12
#define HD    64
#define FF    3072
#define NL    6
#define MTOT  (BATCH*SEQ)        // 4096
#define QKVD  (3*DM)             // 2304

// ---------------- scratch (no cudaMalloc allowed) ----------------
__device__ float g_h  [MTOT*DM];
__device__ float g_qkv[MTOT*QKVD];
__device__ float g_ctx[MTOT*DM];
__device__ float g_mid[MTOT*FF];

typedef unsigned long long u64;

__device__ __forceinline__ u64 ffma2(u64 a, u64 b, u64 c) {
    u64 d;
    asm("fma.rn.f32x2 %0,%1,%2,%3;" : "=l"(d) : "l"(a), "l"(b), "l"(c));
    return d;
}
__device__ __forceinline__ u64 pack_dup(float x) {
    u64 d;
    asm("mov.b64 %0,{%1,%1};" : "=l"(d) : "r"(__float_as_uint(x)));
    return d;
}
__device__ __forceinline__ float lo32(u64 v) { return __uint_as_float((unsigned)(v & 0xffffffffull)); }
__device__ __forceinline__ float hi32(u64 v) { return __uint_as_float((unsigned)(v >> 32)); }

// ---------------- positional encoding add ----------------
__global__ void pos_add_kernel(const float* __restrict__ x, float* __restrict__ out) {
    int row = blockIdx.x;
    int s = row & (SEQ - 1);
    const float c = -logf(10000.0f) / (float)DM;
    for (int d = threadIdx.x; d < DM; d += blockDim.x) {
        int i2 = d & ~1;
        float ang = (float)s * expf((float)i2 * c);
        float pe = (d & 1) ? cosf(ang) : sinf(ang);
        out[(size_t)row*DM + d] = x[(size_t)row*DM + d] + pe;
    }
}

// ---------------- fp32 SGEMM, double-buffered, packed f32x2, dup-A ----------------
// BM=BN=128, BK=16, 256 threads, 8x8 microtile
#define ALD 260   // dup-A row: 256 floats + pad 4 (2-way-max fill conflicts, aligned reads)
__global__ __launch_bounds__(256, 2)
void sgemm_kernel(const float* __restrict__ A, const float* __restrict__ B,
                  const float* __restrict__ bias, float* __restrict__ C,
                  int M, int N, int K, int relu)
{
    __shared__ float As[2][16][ALD];   // [k][2m]/[2m+1] duplicated
    __shared__ float Bs[2][16][128];

    const int tid = threadIdx.x;
    const int tx = tid & 15;
    const int ty = tid >> 4;
    const int m0 = blockIdx.y * 128;
    const int n0 = blockIdx.x * 128;

    const int am0 = tid >> 2;            // 0..63
    const int ak  = (tid & 3) << 2;
    const int bk0 = tid >> 5;            // 0..7
    const int bn  = (tid & 31) << 2;

    const float* Abase = A + (size_t)m0 * K + ak;
    const float* Bbase = B + n0 + bn;

    float4 pa[2], pb[2];
    pa[0] = *(const float4*)(Abase + (size_t)am0*K);
    pa[1] = *(const float4*)(Abase + (size_t)(am0+64)*K);
    pb[0] = *(const float4*)(Bbase + (size_t)bk0*N);
    pb[1] = *(const float4*)(Bbase + (size_t)(bk0+8)*N);

    {
        // stage tile 0
#pragma unroll
        for (int i = 0; i < 2; i++) {
            int m = am0 + i*64;
            float4 v = pa[i];
            *(float2*)&As[0][ak+0][2*m] = make_float2(v.x, v.x);
            *(float2*)&As[0][ak+1][2*m] = make_float2(v.y, v.y);
            *(float2*)&As[0][ak+2][2*m] = make_float2(v.z, v.z);
            *(float2*)&As[0][ak+3][2*m] = make_float2(v.w, v.w);
            *(float4*)&Bs[0][bk0 + i*8][bn] = pb[i];
        }
    }
    __syncthreads();

    u64 acc[8][4];
#pragma unroll
    for (int i = 0; i < 8; i++)
#pragma unroll
        for (int j = 0; j < 4; j++) acc[i][j] = 0ull;

    const int nt = K >> 4;
    int buf = 0;
    for (int t = 0; t < nt; t++) {
        if (t + 1 < nt) {
            int k0 = (t + 1) << 4;
            pa[0] = *(const float4*)(Abase + (size_t)am0*K + k0);
            pa[1] = *(const float4*)(Abase + (size_t)(am0+64)*K + k0);
            pb[0] = *(const float4*)(Bbase + (size_t)(k0 + bk0)*N);
            pb[1] = *(const float4*)(Bbase + (size_t)(k0 + bk0 + 8)*N);
        }
#pragma unroll
        for (int kk = 0; kk < 16; kk++) {
            ulonglong2 a0 = *(const ulonglong2*)&As[buf][kk][ty*16 + 0];
            ulonglong2 a1 = *(const ulonglong2*)&As[buf][kk][ty*16 + 4];
            ulonglong2 a2 = *(const ulonglong2*)&As[buf][kk][ty*16 + 8];
            ulonglong2 a3 = *(const ulonglong2*)&As[buf][kk][ty*16 + 12];
            ulonglong2 b0 = *(const ulonglong2*)&Bs[buf][kk][tx*8];
            ulonglong2 b1 = *(const ulonglong2*)&Bs[buf][kk][tx*8 + 4];
            u64 ad[8] = { a0.x, a0.y, a1.x, a1.y, a2.x, a2.y, a3.x, a3.y };
#pragma unroll
            for (int i = 0; i < 8; i++) {
                acc[i][0] = ffma2(ad[i], b0.x, acc[i][0]);
                acc[i][1] = ffma2(ad[i], b0.y, acc[i][1]);
                acc[i][2] = ffma2(ad[i], b1.x, acc[i][2]);
                acc[i][3] = ffma2(ad[i], b1.y, acc[i][3]);
            }
        }
        if (t + 1 < nt) {
            int nb = buf ^ 1;
#pragma unroll
            for (int i = 0; i < 2; i++) {
                int m = am0 + i*64;
                float4 v = pa[i];
                *(float2*)&As[nb][ak+0][2*m] = make_float2(v.x, v.x);
                *(float2*)&As[nb][ak+1][2*m] = make_float2(v.y, v.y);
                *(float2*)&As[nb][ak+2][2*m] = make_float2(v.z, v.z);
                *(float2*)&As[nb][ak+3][2*m] = make_float2(v.w, v.w);
                *(float4*)&Bs[nb][bk0 + i*8][bn] = pb[i];
            }
            __syncthreads();
            buf = nb;
        }
    }

#pragma unroll
    for (int i = 0; i < 8; i++) {
        int row = m0 + ty*8 + i;
#pragma unroll
        for (int j = 0; j < 4; j++) {
            int col = n0 + tx*8 + j*2;
            float c0 = lo32(acc[i][j]) + bias[col];
            float c1 = hi32(acc[i][j]) + bias[col + 1];
            if (relu) { c0 = fmaxf(c0, 0.f); c1 = fmaxf(c1, 0.f); }
            *(float2*)&C[(size_t)row*N + col] = make_float2(c0, c1);
        }
    }
}

// ---------------- attention: f32x2 everywhere ----------------
// block = (q_tile of 32, head, batch); 256 threads
#define P_LD  1032
#define KS_LD 68
#define ATT_SMEM ((32*64 + 128*KS_LD + 32*P_LD) * sizeof(float))  // ~175 KB
__global__ __launch_bounds__(256)
void attn_kernel(const float* __restrict__ qkv, float* __restrict__ ctx)
{
    extern __shared__ float sm[];
    float* Qs = sm;                       // [32][64]
    float* Ks = sm + 32*64;               // [128][KS_LD] for K; reused as [128][64] for V
    float* P  = sm + 32*64 + 128*KS_LD;   // [32][P_LD]

    const int tid = threadIdx.x;
    const int q0  = blockIdx.x * 32;
    const int h   = blockIdx.y;
    const int b   = blockIdx.z;
    const size_t baseQ = (size_t)b*SEQ*QKVD + h*HD;
    const size_t baseK = baseQ + DM;
    const size_t baseV = baseQ + 2*DM;

    // load Q tile 32x64 (row-major)
    for (int f = tid; f < 32*16; f += 256) {
        int r = f >> 4, c4 = (f & 15) << 2;
        *(float4*)(Qs + r*64 + c4) =
            *(const float4*)(qkv + baseQ + (size_t)(q0 + r)*QKVD + c4);
    }

    // ---- scores: pair along d (reduction axis) -> pure f32x2, no transposes ----
    const int txk = tid & 63;            // k cols: txk, txk+64
    const int tyq = tid >> 6;            // row group: rows tyq*8 .. +7
    const float scale = 0.125f;
    for (int kt = 0; kt < 8; kt++) {
        for (int f = tid; f < 128*16; f += 256) {
            int r = f >> 4, c4 = (f & 15) << 2;
            *(float4*)&Ks[r*KS_LD + c4] =
                *(const float4*)(qkv + baseK + (size_t)(kt*128 + r)*QKVD + c4);
        }
        __syncthreads();
        u64 acc[8][2];
#pragma unroll
        for (int i = 0; i < 8; i++) { acc[i][0] = 0ull; acc[i][1] = 0ull; }
#pragma unroll 2
        for (int d4 = 0; d4 < 64; d4 += 4) {
            ulonglong2 k0 = *(const ulonglong2*)&Ks[txk*KS_LD + d4];
            ulonglong2 k1 = *(const ulonglong2*)&Ks[(txk+64)*KS_LD + d4];
#pragma unroll
            for (int i = 0; i < 8; i++) {
                ulonglong2 q = *(const ulonglong2*)&Qs[(tyq*8 + i)*64 + d4];
                acc[i][0] = ffma2(q.x, k0.x, acc[i][0]);
                acc[i][0] = ffma2(q.y, k0.y, acc[i][0]);
                acc[i][1] = ffma2(q.x, k1.x, acc[i][1]);
                acc[i][1] = ffma2(q.y, k1.y, acc[i][1]);
            }
        }
#pragma unroll
        for (int i = 0; i < 8; i++) {
#pragma unroll
            for (int j = 0; j < 2; j++)
                P[(tyq*8 + i)*P_LD + kt*128 + txk + 64*j] =
                    (lo32(acc[i][j]) + hi32(acc[i][j])) * scale;
        }
        __syncthreads();
    }

    // ---- softmax + clip per row (warp per row) ----
    const int warp = tid >> 5, lane = tid & 31;
    for (int r = warp; r < 32; r += 8) {
        float* row = P + r*P_LD;
        float m = -INFINITY;
        for (int t = lane; t < 1024; t += 32) m = fmaxf(m, row[t]);
#pragma unroll
        for (int o = 16; o; o >>= 1) m = fmaxf(m, __shfl_xor_sync(~0u, m, o));
        float s = 0.f;
        for (int t = lane; t < 1024; t += 32) { float e = __expf(row[t] - m); row[t] = e; s += e; }
#pragma unroll
        for (int o = 16; o; o >>= 1) s += __shfl_xor_sync(~0u, s, o);
        float inv = 1.f / s;
        for (int t = lane; t < 1024; t += 32)
            row[t] = fminf(fmaxf(row[t]*inv, 1e-6f), 1.f);
    }
    __syncthreads();

    // ---- O = P @ V : pair along output-d, dup'd P scalars ----
    const int txo = tid & 15;            // d pairs: 2*(txo+16j)
    const int tyo = tid >> 4;            // rows tyo*2 + i
    u64 oacc[2][2] = { {0ull,0ull}, {0ull,0ull} };
    for (int vt = 0; vt < 8; vt++) {
        for (int f = tid; f < 128*16; f += 256) {
            int r = f >> 4, c4 = (f & 15) << 2;
            *(float4*)&Ks[r*64 + c4] =
                *(const float4*)(qkv + baseV + (size_t)(vt*128 + r)*QKVD + c4);
        }
        __syncthreads();
#pragma unroll 4
        for (int k = 0; k < 128; k++) {
            u64 p0 = pack_dup(P[(tyo*2 + 0)*P_LD + vt*128 + k]);
            u64 p1 = pack_dup(P[(tyo*2 + 1)*P_LD + vt*128 + k]);
#pragma unroll
            for (int j = 0; j < 2; j++) {
                u64 v = *(const u64*)&Ks[k*64 + 2*(txo + 16*j)];
                oacc[0][j] = ffma2(p0, v, oacc[0][j]);
                oacc[1][j] = ffma2(p1, v, oacc[1][j]);
            }
        }
        __syncthreads();
    }
#pragma unroll
    for (int i = 0; i < 2; i++)
#pragma unroll
        for (int j = 0; j < 2; j++)
            *(float2*)&ctx[((size_t)b*SEQ + q0 + tyo*2 + i)*DM + h*HD + 2*(txo + 16*j)] =
                make_float2(lo32(oacc[i][j]), hi32(oacc[i][j]));
}

// ---------------- LayerNorm ----------------
__global__ __launch_bounds__(256)
void ln_kernel(const float* __restrict__ base, const float* __restrict__ delta,
               const float* __restrict__ g, const float* __restrict__ bta,
               float* __restrict__ out)
{
    __shared__ float rowv[DM];
    __shared__ float red[256];
    int row = blockIdx.x, tid = threadIdx.x;
    float local = 0.f;
    for (int d = tid; d < DM; d += 256) {
        float v = base[(size_t)row*DM + d];
        if (delta) v += delta[(size_t)row*DM + d];
        rowv[d] = v; local += v;
    }
    red[tid] = local; __syncthreads();
#pragma unroll
    for (int o = 128; o; o >>= 1) { if (tid < o) red[tid] += red[tid + o]; __syncthreads(); }
    float mean = red[0] * (1.0f/DM);
    __syncthreads();
    local = 0.f;
    for (int d = tid; d < DM; d += 256) { float dv = rowv[d] - mean; local += dv*dv; }
    red[tid] = local; __syncthreads();
#pragma unroll
    for (int o = 128; o; o >>= 1) { if (tid < o) red[tid] += red[tid + o]; __syncthreads(); }
    float inv = rsqrtf(red[0] * (1.0f/DM) + 1e-5f);
    for (int d = tid; d < DM; d += 256)
        out[(size_t)row*DM + d] = (rowv[d] - mean)*inv*g[d] + bta[d];
}

// ---------------- orchestration ----------------
extern "C" void kernel_launch(void* const* d_in, const int* in_sizes, int n_in,
                              void* d_out, int out_size)
{
    const float* x    = (const float*)d_in[0];
    const float* Wqkv = (const float*)d_in[1];
    const float* bqkv = (const float*)d_in[2];
    const float* Wo   = (const float*)d_in[3];
    const float* bo   = (const float*)d_in[4];
    const float* ln1g = (const float*)d_in[5];
    const float* ln1b = (const float*)d_in[6];
    const float* W1   = (const float*)d_in[7];
    const float* b1   = (const float*)d_in[8];
    const float* W2   = (const float*)d_in[9];
    const float* b2   = (const float*)d_in[10];
    const float* ln2g = (const float*)d_in[11];
    const float* ln2b = (const float*)d_in[12];
    const float* lnfg = (const float*)d_in[13];
    const float* lnfb = (const float*)d_in[14];
    float* out = (float*)d_out;

    float *h, *qkv, *ctx, *mid;
    cudaGetSymbolAddress((void**)&h,   g_h);
    cudaGetSymbolAddress((void**)&qkv, g_qkv);
    cudaGetSymbolAddress((void**)&ctx, g_ctx);
    cudaGetSymbolAddress((void**)&mid, g_mid);

    cudaFuncSetAttribute(attn_kernel, cudaFuncAttributeMaxDynamicSharedMemorySize,
                         (int)ATT_SMEM);

    pos_add_kernel<<<MTOT, 256>>>(x, h);

    for (int l = 0; l < NL; l++) {
        sgemm_kernel<<<dim3(QKVD/128, MTOT/128), 256>>>(
            h, Wqkv + (size_t)l*DM*QKVD, bqkv + (size_t)l*QKVD, qkv,
            MTOT, QKVD, DM, 0);
        attn_kernel<<<dim3(SEQ/32, NH, BATCH), 256, ATT_SMEM>>>(qkv, ctx);
        sgemm_kernel<<<dim3(DM/128, MTOT/128), 256>>>(
            ctx, Wo + (size_t)l*DM*DM, bo + (size_t)l*DM, mid,
            MTOT, DM, DM, 0);
        ln_kernel<<<MTOT, 256>>>(h, mid, ln1g + (size_t)l*DM, ln1b + (size_t)l*DM, h);
        sgemm_kernel<<<dim3(FF/128, MTOT/128), 256>>>(
            h, W1 + (size_t)l*DM*FF, b1 + (size_t)l*FF, mid,
            MTOT, FF, DM, 1);
        sgemm_kernel<<<dim3(DM/128, MTOT/128), 256>>>(
            mid, W2 + (size_t)l*FF*DM, b2 + (size_t)l*DM, ctx,
            MTOT, DM, FF, 0);
        ln_kernel<<<MTOT, 256>>>(h, ctx, ln2g + (size_t)l*DM, ln2b + (size_t)l*DM, h);
    }

    ln_kernel<<<MTOT, 256>>>(h, nullptr, lnfg, lnfb, out);
}

// round 7
// speedup vs baseline: 1.8206x; 1.8206x over previous
#include <cuda_runtime.h>
#include <cuda_bf16.h>
#include <math.h>
#include <stdint.h>

#define BATCH 4
#define SEQ   1024
#define DM    768
#define NH    12
#define HD    64
#define FF    3072
#define NL    6
#define MTOT  (BATCH*SEQ)        // 4096
#define QKVD  (3*DM)             // 2304

typedef unsigned long long u64;
typedef __nv_bfloat16 bf16;

// ---------------- scratch (no cudaMalloc allowed) ----------------
__device__ float g_h  [MTOT*DM];
__device__ float g_qkv[MTOT*QKVD];
__device__ float g_ctx[MTOT*DM];
__device__ float g_mid[MTOT*FF];
__device__ bf16  g_ah [MTOT*FF];
__device__ bf16  g_al [MTOT*FF];
__device__ bf16  g_wqkvT_h[NL*QKVD*DM], g_wqkvT_l[NL*QKVD*DM];   // [N][K]
__device__ bf16  g_woT_h  [NL*DM*DM],   g_woT_l  [NL*DM*DM];
__device__ bf16  g_w1T_h  [NL*FF*DM],   g_w1T_l  [NL*FF*DM];
__device__ bf16  g_w2T_h  [NL*DM*FF],   g_w2T_l  [NL*DM*FF];

// ---------------- helpers ----------------
__device__ __forceinline__ uint32_t smem_u32(const void* p) {
    uint32_t a;
    asm("{ .reg .u64 t; cvta.to.shared.u64 t, %1; cvt.u32.u64 %0, t; }" : "=r"(a) : "l"(p));
    return a;
}
__device__ __forceinline__ void cpasync16(uint32_t s, const void* g) {
    asm volatile("cp.async.cg.shared.global [%0], [%1], 16;" :: "r"(s), "l"(g));
}
#define CP_COMMIT() asm volatile("cp.async.commit_group;" ::: "memory")
#define CP_WAIT1()  asm volatile("cp.async.wait_group 1;" ::: "memory")
#define CP_WAIT0()  asm volatile("cp.async.wait_group 0;" ::: "memory")

__device__ __forceinline__ void ldmx4(uint32_t* r, uint32_t a) {
    asm volatile("ldmatrix.sync.aligned.m8n8.x4.shared.b16 {%0,%1,%2,%3}, [%4];"
        : "=r"(r[0]), "=r"(r[1]), "=r"(r[2]), "=r"(r[3]) : "r"(a));
}
__device__ __forceinline__ void ldmx2(uint32_t* r, uint32_t a) {
    asm volatile("ldmatrix.sync.aligned.m8n8.x2.shared.b16 {%0,%1}, [%2];"
        : "=r"(r[0]), "=r"(r[1]) : "r"(a));
}
__device__ __forceinline__ void mma16816(float* c, const uint32_t* a, const uint32_t* b) {
    asm volatile("mma.sync.aligned.m16n8k16.row.col.f32.bf16.bf16.f32 "
        "{%0,%1,%2,%3}, {%4,%5,%6,%7}, {%8,%9}, {%0,%1,%2,%3};"
        : "+f"(c[0]), "+f"(c[1]), "+f"(c[2]), "+f"(c[3])
        : "r"(a[0]), "r"(a[1]), "r"(a[2]), "r"(a[3]), "r"(b[0]), "r"(b[1]));
}

__device__ __forceinline__ u64 ffma2(u64 a, u64 b, u64 c) {
    u64 d; asm("fma.rn.f32x2 %0,%1,%2,%3;" : "=l"(d) : "l"(a), "l"(b), "l"(c)); return d;
}
__device__ __forceinline__ u64 pack_dup(float x) {
    u64 d; asm("mov.b64 %0,{%1,%1};" : "=l"(d) : "r"(__float_as_uint(x))); return d;
}
__device__ __forceinline__ float lo32(u64 v) { return __uint_as_float((unsigned)(v & 0xffffffffull)); }
__device__ __forceinline__ float hi32(u64 v) { return __uint_as_float((unsigned)(v >> 32)); }

// ---------------- split kernels ----------------
__global__ void asplit_kernel(const float* __restrict__ x, bf16* __restrict__ h,
                              bf16* __restrict__ l) {
    int i = (blockIdx.x * 256 + threadIdx.x) * 4;
    float4 v = *(const float4*)(x + i);
    bf16 h0 = __float2bfloat16(v.x), h1 = __float2bfloat16(v.y);
    bf16 h2 = __float2bfloat16(v.z), h3 = __float2bfloat16(v.w);
    __nv_bfloat162 ph0; ph0.x = h0; ph0.y = h1;
    __nv_bfloat162 ph1; ph1.x = h2; ph1.y = h3;
    *(__nv_bfloat162*)(h + i)     = ph0;
    *(__nv_bfloat162*)(h + i + 2) = ph1;
    __nv_bfloat162 pl0, pl1;
    pl0.x = __float2bfloat16(v.x - __bfloat162float(h0));
    pl0.y = __float2bfloat16(v.y - __bfloat162float(h1));
    pl1.x = __float2bfloat16(v.z - __bfloat162float(h2));
    pl1.y = __float2bfloat16(v.w - __bfloat162float(h3));
    *(__nv_bfloat162*)(l + i)     = pl0;
    *(__nv_bfloat162*)(l + i + 2) = pl1;
}

// transpose-split: W[K][N] fp32 -> Th,Tl [N][K] bf16
__global__ __launch_bounds__(256)
void wsplit_kernel(const float* __restrict__ W, bf16* __restrict__ Th,
                   bf16* __restrict__ Tl, int K, int N) {
    __shared__ float tile[32][33];
    int nb = blockIdx.x * 32, kb = blockIdx.y * 32;
    int tx = threadIdx.x & 31, ty = threadIdx.x >> 5;
    for (int r = ty; r < 32; r += 8)
        tile[r][tx] = W[(size_t)(kb + r) * N + nb + tx];
    __syncthreads();
    for (int r = ty; r < 32; r += 8) {
        float v = tile[tx][r];
        bf16 hv = __float2bfloat16(v);
        Th[(size_t)(nb + r) * K + kb + tx] = hv;
        Tl[(size_t)(nb + r) * K + kb + tx] = __float2bfloat16(v - __bfloat162float(hv));
    }
}

// ---------------- mma.sync bf16-split GEMM ----------------
// C[M,N] = Ah@BhT + Al@BhT + Ah@BlT + bias (opt relu)
// A*: [M][K] bf16; B*T: [N][K] bf16. Block 128x128x32, 8 warps (2m x 4n), warp 64x32.
#define ROWB  80                 // smem row bytes: 32 bf16 + 8 pad
#define TILEB (128*ROWB)         // 10240 B per tile
#define GEMM_SMEM (8*TILEB)      // 4 tiles x 2 buffers = 81920 B
__global__ __launch_bounds__(256)
void gemm_bf16_kernel(const bf16* __restrict__ Ah, const bf16* __restrict__ Al,
                      const bf16* __restrict__ Bh, const bf16* __restrict__ Bl,
                      const float* __restrict__ bias, float* __restrict__ C,
                      int M, int N, int K, int relu)
{
    extern __shared__ char smem[];
    const uint32_t sb = smem_u32(smem);
    const int tid = threadIdx.x, lane = tid & 31, wid = tid >> 5;
    const int wm = (wid & 1) * 64, wn = (wid >> 1) * 32;
    const int m0 = blockIdx.y * 128, n0 = blockIdx.x * 128;

    const bf16* gsrc[4] = { Ah + (size_t)m0*K, Al + (size_t)m0*K,
                            Bh + (size_t)n0*K, Bl + (size_t)n0*K };

    const int lrow = tid >> 1;           // 0..127
    const int lc0  = (tid & 1) * 2;      // 16B-vec index 0 or 2

    // ldmatrix per-lane offsets
    const int aMoff = ((lane >> 3) & 1) * 8 + (lane & 7);
    const int aKby  = (lane >> 4) * 16;              // 8 bf16 = 16 B
    const int bNoff = lane & 7;
    const int bKby  = ((lane >> 3) & 1) * 16;

    const int nchunk = K >> 5;

    // preload chunk 0 into buf 0
    {
        uint32_t dst = sb;
#pragma unroll
        for (int v = 0; v < 4; v++) {
            const bf16* g = gsrc[v] + (size_t)lrow*K + lc0*8;
            uint32_t s = dst + v*TILEB + lrow*ROWB + lc0*16;
            cpasync16(s, g);
            cpasync16(s + 16, g + 8);
        }
        CP_COMMIT();
    }

    float acc[4][4][4];
#pragma unroll
    for (int a = 0; a < 4; a++)
#pragma unroll
        for (int b = 0; b < 4; b++)
#pragma unroll
            for (int c = 0; c < 4; c++) acc[a][b][c] = 0.f;

    for (int t = 0; t < nchunk; t++) {
        if (t + 1 < nchunk) {
            int k0 = (t + 1) * 32;
            uint32_t dst = sb + ((t + 1) & 1) * 4*TILEB;
#pragma unroll
            for (int v = 0; v < 4; v++) {
                const bf16* g = gsrc[v] + (size_t)lrow*K + k0 + lc0*8;
                uint32_t s = dst + v*TILEB + lrow*ROWB + lc0*16;
                cpasync16(s, g);
                cpasync16(s + 16, g + 8);
            }
            CP_COMMIT();
            CP_WAIT1();
        } else {
            CP_WAIT0();
        }
        __syncthreads();

        uint32_t base = sb + (t & 1) * 4*TILEB;
#pragma unroll
        for (int kk = 0; kk < 2; kk++) {
            uint32_t bh[4][2], bl[4][2];
#pragma unroll
            for (int nt = 0; nt < 4; nt++) {
                uint32_t baddr = base + 2*TILEB + (wn + nt*8 + bNoff)*ROWB + kk*32 + bKby;
                ldmx2(bh[nt], baddr);
                ldmx2(bl[nt], baddr + TILEB);
            }
#pragma unroll
            for (int mt = 0; mt < 4; mt++) {
                uint32_t ah[4], al[4];
                uint32_t aaddr = base + (wm + mt*16 + aMoff)*ROWB + kk*32 + aKby;
                ldmx4(ah, aaddr);
                ldmx4(al, aaddr + TILEB);
#pragma unroll
                for (int nt = 0; nt < 4; nt++) {
                    mma16816(acc[mt][nt], ah, bh[nt]);
                    mma16816(acc[mt][nt], al, bh[nt]);
                    mma16816(acc[mt][nt], ah, bl[nt]);
                }
            }
        }
        __syncthreads();
    }

    // epilogue
    const int r0 = lane >> 2, cq = (lane & 3) * 2;
#pragma unroll
    for (int mt = 0; mt < 4; mt++) {
#pragma unroll
        for (int nt = 0; nt < 4; nt++) {
            int row = m0 + wm + mt*16 + r0;
            int col = n0 + wn + nt*8 + cq;
            float b0 = bias[col], b1 = bias[col + 1];
            float c0 = acc[mt][nt][0] + b0, c1 = acc[mt][nt][1] + b1;
            float c2 = acc[mt][nt][2] + b0, c3 = acc[mt][nt][3] + b1;
            if (relu) {
                c0 = fmaxf(c0, 0.f); c1 = fmaxf(c1, 0.f);
                c2 = fmaxf(c2, 0.f); c3 = fmaxf(c3, 0.f);
            }
            *(float2*)&C[(size_t)row*N + col]       = make_float2(c0, c1);
            *(float2*)&C[(size_t)(row + 8)*N + col] = make_float2(c2, c3);
        }
    }
}

// ---------------- positional encoding add ----------------
__global__ void pos_add_kernel(const float* __restrict__ x, float* __restrict__ out) {
    int row = blockIdx.x;
    int s = row & (SEQ - 1);
    const float c = -logf(10000.0f) / (float)DM;
    for (int d = threadIdx.x; d < DM; d += blockDim.x) {
        int i2 = d & ~1;
        float ang = (float)s * expf((float)i2 * c);
        float pe = (d & 1) ? cosf(ang) : sinf(ang);
        out[(size_t)row*DM + d] = x[(size_t)row*DM + d] + pe;
    }
}

// ---------------- attention (f32x2 SIMT) ----------------
#define P_LD  1032
#define KS_LD 68
#define ATT_SMEM ((32*64 + 128*KS_LD + 32*P_LD) * sizeof(float))
__global__ __launch_bounds__(256)
void attn_kernel(const float* __restrict__ qkv, float* __restrict__ ctx)
{
    extern __shared__ float sm[];
    float* Qs = sm;
    float* Ks = sm + 32*64;
    float* P  = sm + 32*64 + 128*KS_LD;

    const int tid = threadIdx.x;
    const int q0  = blockIdx.x * 32;
    const int h   = blockIdx.y;
    const int b   = blockIdx.z;
    const size_t baseQ = (size_t)b*SEQ*QKVD + h*HD;
    const size_t baseK = baseQ + DM;
    const size_t baseV = baseQ + 2*DM;

    for (int f = tid; f < 32*16; f += 256) {
        int r = f >> 4, c4 = (f & 15) << 2;
        *(float4*)(Qs + r*64 + c4) =
            *(const float4*)(qkv + baseQ + (size_t)(q0 + r)*QKVD + c4);
    }

    const int txk = tid & 63;
    const int tyq = tid >> 6;
    const float scale = 0.125f;
    for (int kt = 0; kt < 8; kt++) {
        for (int f = tid; f < 128*16; f += 256) {
            int r = f >> 4, c4 = (f & 15) << 2;
            *(float4*)&Ks[r*KS_LD + c4] =
                *(const float4*)(qkv + baseK + (size_t)(kt*128 + r)*QKVD + c4);
        }
        __syncthreads();
        u64 acc[8][2];
#pragma unroll
        for (int i = 0; i < 8; i++) { acc[i][0] = 0ull; acc[i][1] = 0ull; }
#pragma unroll 2
        for (int d4 = 0; d4 < 64; d4 += 4) {
            ulonglong2 k0 = *(const ulonglong2*)&Ks[txk*KS_LD + d4];
            ulonglong2 k1 = *(const ulonglong2*)&Ks[(txk+64)*KS_LD + d4];
#pragma unroll
            for (int i = 0; i < 8; i++) {
                ulonglong2 q = *(const ulonglong2*)&Qs[(tyq*8 + i)*64 + d4];
                acc[i][0] = ffma2(q.x, k0.x, acc[i][0]);
                acc[i][0] = ffma2(q.y, k0.y, acc[i][0]);
                acc[i][1] = ffma2(q.x, k1.x, acc[i][1]);
                acc[i][1] = ffma2(q.y, k1.y, acc[i][1]);
            }
        }
#pragma unroll
        for (int i = 0; i < 8; i++) {
#pragma unroll
            for (int j = 0; j < 2; j++)
                P[(tyq*8 + i)*P_LD + kt*128 + txk + 64*j] =
                    (lo32(acc[i][j]) + hi32(acc[i][j])) * scale;
        }
        __syncthreads();
    }

    const int warp = tid >> 5, lane = tid & 31;
    for (int r = warp; r < 32; r += 8) {
        float* row = P + r*P_LD;
        float m = -INFINITY;
        for (int t = lane; t < 1024; t += 32) m = fmaxf(m, row[t]);
#pragma unroll
        for (int o = 16; o; o >>= 1) m = fmaxf(m, __shfl_xor_sync(~0u, m, o));
        float s = 0.f;
        for (int t = lane; t < 1024; t += 32) { float e = __expf(row[t] - m); row[t] = e; s += e; }
#pragma unroll
        for (int o = 16; o; o >>= 1) s += __shfl_xor_sync(~0u, s, o);
        float inv = 1.f / s;
        for (int t = lane; t < 1024; t += 32)
            row[t] = fminf(fmaxf(row[t]*inv, 1e-6f), 1.f);
    }
    __syncthreads();

    const int txo = tid & 15;
    const int tyo = tid >> 4;
    u64 oacc[2][2] = { {0ull,0ull}, {0ull,0ull} };
    for (int vt = 0; vt < 8; vt++) {
        for (int f = tid; f < 128*16; f += 256) {
            int r = f >> 4, c4 = (f & 15) << 2;
            *(float4*)&Ks[r*64 + c4] =
                *(const float4*)(qkv + baseV + (size_t)(vt*128 + r)*QKVD + c4);
        }
        __syncthreads();
#pragma unroll 4
        for (int k = 0; k < 128; k++) {
            u64 p0 = pack_dup(P[(tyo*2 + 0)*P_LD + vt*128 + k]);
            u64 p1 = pack_dup(P[(tyo*2 + 1)*P_LD + vt*128 + k]);
#pragma unroll
            for (int j = 0; j < 2; j++) {
                u64 v = *(const u64*)&Ks[k*64 + 2*(txo + 16*j)];
                oacc[0][j] = ffma2(p0, v, oacc[0][j]);
                oacc[1][j] = ffma2(p1, v, oacc[1][j]);
            }
        }
        __syncthreads();
    }
#pragma unroll
    for (int i = 0; i < 2; i++)
#pragma unroll
        for (int j = 0; j < 2; j++)
            *(float2*)&ctx[((size_t)b*SEQ + q0 + tyo*2 + i)*DM + h*HD + 2*(txo + 16*j)] =
                make_float2(lo32(oacc[i][j]), hi32(oacc[i][j]));
}

// ---------------- LayerNorm ----------------
__global__ __launch_bounds__(256)
void ln_kernel(const float* __restrict__ base, const float* __restrict__ delta,
               const float* __restrict__ g, const float* __restrict__ bta,
               float* __restrict__ out)
{
    __shared__ float rowv[DM];
    __shared__ float red[256];
    int row = blockIdx.x, tid = threadIdx.x;
    float local = 0.f;
    for (int d = tid; d < DM; d += 256) {
        float v = base[(size_t)row*DM + d];
        if (delta) v += delta[(size_t)row*DM + d];
        rowv[d] = v; local += v;
    }
    red[tid] = local; __syncthreads();
#pragma unroll
    for (int o = 128; o; o >>= 1) { if (tid < o) red[tid] += red[tid + o]; __syncthreads(); }
    float mean = red[0] * (1.0f/DM);
    __syncthreads();
    local = 0.f;
    for (int d = tid; d < DM; d += 256) { float dv = rowv[d] - mean; local += dv*dv; }
    red[tid] = local; __syncthreads();
#pragma unroll
    for (int o = 128; o; o >>= 1) { if (tid < o) red[tid] += red[tid + o]; __syncthreads(); }
    float inv = rsqrtf(red[0] * (1.0f/DM) + 1e-5f);
    for (int d = tid; d < DM; d += 256)
        out[(size_t)row*DM + d] = (rowv[d] - mean)*inv*g[d] + bta[d];
}

// ---------------- orchestration ----------------
extern "C" void kernel_launch(void* const* d_in, const int* in_sizes, int n_in,
                              void* d_out, int out_size)
{
    const float* x    = (const float*)d_in[0];
    const float* Wqkv = (const float*)d_in[1];
    const float* bqkv = (const float*)d_in[2];
    const float* Wo   = (const float*)d_in[3];
    const float* bo   = (const float*)d_in[4];
    const float* ln1g = (const float*)d_in[5];
    const float* ln1b = (const float*)d_in[6];
    const float* W1   = (const float*)d_in[7];
    const float* b1   = (const float*)d_in[8];
    const float* W2   = (const float*)d_in[9];
    const float* b2   = (const float*)d_in[10];
    const float* ln2g = (const float*)d_in[11];
    const float* ln2b = (const float*)d_in[12];
    const float* lnfg = (const float*)d_in[13];
    const float* lnfb = (const float*)d_in[14];
    float* out = (float*)d_out;

    float *h, *qkv, *ctx, *mid;
    bf16 *ah, *al, *wqkvTh, *wqkvTl, *woTh, *woTl, *w1Th, *w1Tl, *w2Th, *w2Tl;
    cudaGetSymbolAddress((void**)&h,   g_h);
    cudaGetSymbolAddress((void**)&qkv, g_qkv);
    cudaGetSymbolAddress((void**)&ctx, g_ctx);
    cudaGetSymbolAddress((void**)&mid, g_mid);
    cudaGetSymbolAddress((void**)&ah,  g_ah);
    cudaGetSymbolAddress((void**)&al,  g_al);
    cudaGetSymbolAddress((void**)&wqkvTh, g_wqkvT_h);
    cudaGetSymbolAddress((void**)&wqkvTl, g_wqkvT_l);
    cudaGetSymbolAddress((void**)&woTh, g_woT_h);
    cudaGetSymbolAddress((void**)&woTl, g_woT_l);
    cudaGetSymbolAddress((void**)&w1Th, g_w1T_h);
    cudaGetSymbolAddress((void**)&w1Tl, g_w1T_l);
    cudaGetSymbolAddress((void**)&w2Th, g_w2T_h);
    cudaGetSymbolAddress((void**)&w2Tl, g_w2T_l);

    cudaFuncSetAttribute(attn_kernel, cudaFuncAttributeMaxDynamicSharedMemorySize,
                         (int)ATT_SMEM);
    cudaFuncSetAttribute(gemm_bf16_kernel, cudaFuncAttributeMaxDynamicSharedMemorySize,
                         GEMM_SMEM);

    // ---- weight transpose+split (runs once per launch; part of timed graph) ----
    for (int l = 0; l < NL; l++) {
        wsplit_kernel<<<dim3(QKVD/32, DM/32), 256>>>(
            Wqkv + (size_t)l*DM*QKVD, wqkvTh + (size_t)l*QKVD*DM, wqkvTl + (size_t)l*QKVD*DM, DM, QKVD);
        wsplit_kernel<<<dim3(DM/32, DM/32), 256>>>(
            Wo + (size_t)l*DM*DM, woTh + (size_t)l*DM*DM, woTl + (size_t)l*DM*DM, DM, DM);
        wsplit_kernel<<<dim3(FF/32, DM/32), 256>>>(
            W1 + (size_t)l*DM*FF, w1Th + (size_t)l*FF*DM, w1Tl + (size_t)l*FF*DM, DM, FF);
        wsplit_kernel<<<dim3(DM/32, FF/32), 256>>>(
            W2 + (size_t)l*FF*DM, w2Th + (size_t)l*DM*FF, w2Tl + (size_t)l*DM*FF, FF, DM);
    }

    pos_add_kernel<<<MTOT, 256>>>(x, h);

    for (int l = 0; l < NL; l++) {
        // qkv = h @ Wqkv + bqkv
        asplit_kernel<<<MTOT*DM/1024, 256>>>(h, ah, al);
        gemm_bf16_kernel<<<dim3(QKVD/128, MTOT/128), 256, GEMM_SMEM>>>(
            ah, al, wqkvTh + (size_t)l*QKVD*DM, wqkvTl + (size_t)l*QKVD*DM,
            bqkv + (size_t)l*QKVD, qkv, MTOT, QKVD, DM, 0);
        // attention
        attn_kernel<<<dim3(SEQ/32, NH, BATCH), 256, ATT_SMEM>>>(qkv, ctx);
        // proj = ctx @ Wo + bo
        asplit_kernel<<<MTOT*DM/1024, 256>>>(ctx, ah, al);
        gemm_bf16_kernel<<<dim3(DM/128, MTOT/128), 256, GEMM_SMEM>>>(
            ah, al, woTh + (size_t)l*DM*DM, woTl + (size_t)l*DM*DM,
            bo + (size_t)l*DM, mid, MTOT, DM, DM, 0);
        ln_kernel<<<MTOT, 256>>>(h, mid, ln1g + (size_t)l*DM, ln1b + (size_t)l*DM, h);
        // mid = relu(h @ W1 + b1)
        asplit_kernel<<<MTOT*DM/1024, 256>>>(h, ah, al);
        gemm_bf16_kernel<<<dim3(FF/128, MTOT/128), 256, GEMM_SMEM>>>(
            ah, al, w1Th + (size_t)l*FF*DM, w1Tl + (size_t)l*FF*DM,
            b1 + (size_t)l*FF, mid, MTOT, FF, DM, 1);
        // ffn = mid @ W2 + b2
        asplit_kernel<<<MTOT*FF/1024, 256>>>(mid, ah, al);
        gemm_bf16_kernel<<<dim3(DM/128, MTOT/128), 256, GEMM_SMEM>>>(
            ah, al, w2Th + (size_t)l*DM*FF, w2Tl + (size_t)l*DM*FF,
            b2 + (size_t)l*DM, ctx, MTOT, DM, FF, 0);
        ln_kernel<<<MTOT, 256>>>(h, ctx, ln2g + (size_t)l*DM, ln2b + (size_t)l*DM, h);
    }

    ln_kernel<<<MTOT, 256>>>(h, nullptr, lnfg, lnfb, out);
}

// round 8
// speedup vs baseline: 1.9093x; 1.0487x over previous
#include <cuda_runtime.h>
#include <cuda_bf16.h>
#include <math.h>
#include <stdint.h>

#define BATCH 4
#define SEQ   1024
#define DM    768
#define NH    12
#define HD    64
#define FF    3072
#define NL    6
#define MTOT  (BATCH*SEQ)        // 4096
#define QKVD  (3*DM)             // 2304

typedef unsigned long long u64;
typedef __nv_bfloat16 bf16;

// ---------------- scratch (no cudaMalloc allowed) ----------------
__device__ float g_h  [MTOT*DM];
__device__ float g_qkv[MTOT*QKVD];
__device__ float g_mid[MTOT*DM];      // proj / ffn delta (only DM wide now)
__device__ bf16  g_hh [MTOT*DM],  g_hl [MTOT*DM];     // h splits
__device__ bf16  g_qh [MTOT*QKVD], g_ql [MTOT*QKVD];  // qkv splits
__device__ bf16  g_ch [MTOT*DM],  g_cl [MTOT*DM];     // ctx splits
__device__ bf16  g_mh [MTOT*FF],  g_ml [MTOT*FF];     // ffn-mid splits
__device__ bf16  g_wqkvT_h[NL*QKVD*DM], g_wqkvT_l[NL*QKVD*DM];   // [N][K]
__device__ bf16  g_woT_h  [NL*DM*DM],   g_woT_l  [NL*DM*DM];
__device__ bf16  g_w1T_h  [NL*FF*DM],   g_w1T_l  [NL*FF*DM];
__device__ bf16  g_w2T_h  [NL*DM*FF],   g_w2T_l  [NL*DM*FF];

// ---------------- helpers ----------------
__device__ __forceinline__ uint32_t smem_u32(const void* p) {
    uint32_t a;
    asm("{ .reg .u64 t; cvta.to.shared.u64 t, %1; cvt.u32.u64 %0, t; }" : "=r"(a) : "l"(p));
    return a;
}
__device__ __forceinline__ void cpasync16(uint32_t s, const void* g) {
    asm volatile("cp.async.cg.shared.global [%0], [%1], 16;" :: "r"(s), "l"(g));
}
#define CP_COMMIT() asm volatile("cp.async.commit_group;" ::: "memory")
#define CP_WAIT1()  asm volatile("cp.async.wait_group 1;" ::: "memory")
#define CP_WAIT0()  asm volatile("cp.async.wait_group 0;" ::: "memory")

__device__ __forceinline__ void ldmx4(uint32_t* r, uint32_t a) {
    asm volatile("ldmatrix.sync.aligned.m8n8.x4.shared.b16 {%0,%1,%2,%3}, [%4];"
        : "=r"(r[0]), "=r"(r[1]), "=r"(r[2]), "=r"(r[3]) : "r"(a));
}
__device__ __forceinline__ void ldmx2(uint32_t* r, uint32_t a) {
    asm volatile("ldmatrix.sync.aligned.m8n8.x2.shared.b16 {%0,%1}, [%2];"
        : "=r"(r[0]), "=r"(r[1]) : "r"(a));
}
__device__ __forceinline__ void mma16816(float* c, const uint32_t* a, const uint32_t* b) {
    asm volatile("mma.sync.aligned.m16n8k16.row.col.f32.bf16.bf16.f32 "
        "{%0,%1,%2,%3}, {%4,%5,%6,%7}, {%8,%9}, {%0,%1,%2,%3};"
        : "+f"(c[0]), "+f"(c[1]), "+f"(c[2]), "+f"(c[3])
        : "r"(a[0]), "r"(a[1]), "r"(a[2]), "r"(a[3]), "r"(b[0]), "r"(b[1]));
}

__device__ __forceinline__ u64 ffma2(u64 a, u64 b, u64 c) {
    u64 d; asm("fma.rn.f32x2 %0,%1,%2,%3;" : "=l"(d) : "l"(a), "l"(b), "l"(c)); return d;
}
__device__ __forceinline__ u64 pack_dup(float x) {
    u64 d; asm("mov.b64 %0,{%1,%1};" : "=l"(d) : "r"(__float_as_uint(x))); return d;
}
__device__ __forceinline__ float lo32(u64 v) { return __uint_as_float((unsigned)(v & 0xffffffffull)); }
__device__ __forceinline__ float hi32(u64 v) { return __uint_as_float((unsigned)(v >> 32)); }

__device__ __forceinline__ void split2(float c0, float c1, bf16* ph, bf16* pl) {
    bf16 h0 = __float2bfloat16(c0), h1 = __float2bfloat16(c1);
    __nv_bfloat162 vh; vh.x = h0; vh.y = h1;
    __nv_bfloat162 vl;
    vl.x = __float2bfloat16(c0 - __bfloat162float(h0));
    vl.y = __float2bfloat16(c1 - __bfloat162float(h1));
    *(__nv_bfloat162*)ph = vh;
    *(__nv_bfloat162*)pl = vl;
}

// ---------------- weight transpose-split: W[K][N] fp32 -> Th,Tl [N][K] bf16 ----
__global__ __launch_bounds__(256)
void wsplit_kernel(const float* __restrict__ W, bf16* __restrict__ Th,
                   bf16* __restrict__ Tl, int K, int N) {
    __shared__ float tile[32][33];
    int nb = blockIdx.x * 32, kb = blockIdx.y * 32;
    int tx = threadIdx.x & 31, ty = threadIdx.x >> 5;
    for (int r = ty; r < 32; r += 8)
        tile[r][tx] = W[(size_t)(kb + r) * N + nb + tx];
    __syncthreads();
    for (int r = ty; r < 32; r += 8) {
        float v = tile[tx][r];
        bf16 hv = __float2bfloat16(v);
        Th[(size_t)(nb + r) * K + kb + tx] = hv;
        Tl[(size_t)(nb + r) * K + kb + tx] = __float2bfloat16(v - __bfloat162float(hv));
    }
}

// ---------------- mma.sync bf16-split GEMM + fused epilogue split ----------------
// C = Ah@BhT + Al@BhT + Ah@BlT + bias; optional relu; optional f32 / split outputs.
#define ROWB  80
#define TILEB (128*ROWB)
#define GEMM_SMEM (8*TILEB)
__global__ __launch_bounds__(256)
void gemm_bf16_kernel(const bf16* __restrict__ Ah, const bf16* __restrict__ Al,
                      const bf16* __restrict__ Bh, const bf16* __restrict__ Bl,
                      const float* __restrict__ bias,
                      float* __restrict__ Cf, bf16* __restrict__ Ch, bf16* __restrict__ Cl,
                      int M, int N, int K, int relu)
{
    extern __shared__ char smem[];
    const uint32_t sb = smem_u32(smem);
    const int tid = threadIdx.x, lane = tid & 31, wid = tid >> 5;
    const int wm = (wid & 1) * 64, wn = (wid >> 1) * 32;
    const int m0 = blockIdx.y * 128, n0 = blockIdx.x * 128;

    const bf16* gsrc[4] = { Ah + (size_t)m0*K, Al + (size_t)m0*K,
                            Bh + (size_t)n0*K, Bl + (size_t)n0*K };

    const int lrow = tid >> 1;
    const int lc0  = (tid & 1) * 2;

    const int aMoff = ((lane >> 3) & 1) * 8 + (lane & 7);
    const int aKby  = (lane >> 4) * 16;
    const int bNoff = lane & 7;
    const int bKby  = ((lane >> 3) & 1) * 16;

    const int nchunk = K >> 5;

    {
        uint32_t dst = sb;
#pragma unroll
        for (int v = 0; v < 4; v++) {
            const bf16* g = gsrc[v] + (size_t)lrow*K + lc0*8;
            uint32_t s = dst + v*TILEB + lrow*ROWB + lc0*16;
            cpasync16(s, g);
            cpasync16(s + 16, g + 8);
        }
        CP_COMMIT();
    }

    float acc[4][4][4];
#pragma unroll
    for (int a = 0; a < 4; a++)
#pragma unroll
        for (int b = 0; b < 4; b++)
#pragma unroll
            for (int c = 0; c < 4; c++) acc[a][b][c] = 0.f;

    for (int t = 0; t < nchunk; t++) {
        if (t + 1 < nchunk) {
            int k0 = (t + 1) * 32;
            uint32_t dst = sb + ((t + 1) & 1) * 4*TILEB;
#pragma unroll
            for (int v = 0; v < 4; v++) {
                const bf16* g = gsrc[v] + (size_t)lrow*K + k0 + lc0*8;
                uint32_t s = dst + v*TILEB + lrow*ROWB + lc0*16;
                cpasync16(s, g);
                cpasync16(s + 16, g + 8);
            }
            CP_COMMIT();
            CP_WAIT1();
        } else {
            CP_WAIT0();
        }
        __syncthreads();

        uint32_t base = sb + (t & 1) * 4*TILEB;
#pragma unroll
        for (int kk = 0; kk < 2; kk++) {
            uint32_t bh[4][2], bl[4][2];
#pragma unroll
            for (int nt = 0; nt < 4; nt++) {
                uint32_t baddr = base + 2*TILEB + (wn + nt*8 + bNoff)*ROWB + kk*32 + bKby;
                ldmx2(bh[nt], baddr);
                ldmx2(bl[nt], baddr + TILEB);
            }
#pragma unroll
            for (int mt = 0; mt < 4; mt++) {
                uint32_t ah[4], al[4];
                uint32_t aaddr = base + (wm + mt*16 + aMoff)*ROWB + kk*32 + aKby;
                ldmx4(ah, aaddr);
                ldmx4(al, aaddr + TILEB);
#pragma unroll
                for (int nt = 0; nt < 4; nt++) {
                    mma16816(acc[mt][nt], ah, bh[nt]);
                    mma16816(acc[mt][nt], al, bh[nt]);
                    mma16816(acc[mt][nt], ah, bl[nt]);
                }
            }
        }
        __syncthreads();
    }

    // epilogue (optional f32 / split outputs)
    const int r0 = lane >> 2, cq = (lane & 3) * 2;
#pragma unroll
    for (int mt = 0; mt < 4; mt++) {
#pragma unroll
        for (int nt = 0; nt < 4; nt++) {
            int row = m0 + wm + mt*16 + r0;
            int col = n0 + wn + nt*8 + cq;
            float b0 = bias[col], b1 = bias[col + 1];
            float c0 = acc[mt][nt][0] + b0, c1 = acc[mt][nt][1] + b1;
            float c2 = acc[mt][nt][2] + b0, c3 = acc[mt][nt][3] + b1;
            if (relu) {
                c0 = fmaxf(c0, 0.f); c1 = fmaxf(c1, 0.f);
                c2 = fmaxf(c2, 0.f); c3 = fmaxf(c3, 0.f);
            }
            size_t o0 = (size_t)row*N + col, o1 = (size_t)(row + 8)*N + col;
            if (Cf) {
                *(float2*)&Cf[o0] = make_float2(c0, c1);
                *(float2*)&Cf[o1] = make_float2(c2, c3);
            }
            if (Ch) {
                split2(c0, c1, Ch + o0, Cl + o0);
                split2(c2, c3, Ch + o1, Cl + o1);
            }
        }
    }
}

// ---------------- positional encoding add (+ split) ----------------
__global__ void pos_add_kernel(const float* __restrict__ x, float* __restrict__ out,
                               bf16* __restrict__ oh, bf16* __restrict__ ol) {
    int row = blockIdx.x;
    int s = row & (SEQ - 1);
    const float c = -logf(10000.0f) / (float)DM;
    for (int d = threadIdx.x; d < DM; d += blockDim.x) {
        int i2 = d & ~1;
        float ang = (float)s * expf((float)i2 * c);
        float pe = (d & 1) ? cosf(ang) : sinf(ang);
        float v = x[(size_t)row*DM + d] + pe;
        out[(size_t)row*DM + d] = v;
        bf16 hv = __float2bfloat16(v);
        oh[(size_t)row*DM + d] = hv;
        ol[(size_t)row*DM + d] = __float2bfloat16(v - __bfloat162float(hv));
    }
}

// ---------------- attention: tensor-core scores + SIMT softmax/PV ----------------
// block = (q_tile of 32, head, batch); 256 threads (8 warps)
#define P_LD   1032
#define QPITCH 72                 // bf16 elems per Q/K smem row (144 B)
#define SM_P   0
#define SM_QH  (32*P_LD*4)                       // 132096
#define SM_QL  (SM_QH + 32*QPITCH*2)             // +4608
#define SM_KH  (SM_QL + 32*QPITCH*2)             // +4608
#define SM_KL  (SM_KH + 128*QPITCH*2)            // +18432
#define SM_V   SM_KH                              // V fp32 overlays K region (32KB<=36.8KB)
#define ATT_SMEM (SM_KL + 128*QPITCH*2)          // 178176 B
__global__ __launch_bounds__(256)
void attn_kernel(const float* __restrict__ qkv,
                 const bf16* __restrict__ qkh, const bf16* __restrict__ qkl,
                 bf16* __restrict__ ctxh, bf16* __restrict__ ctxl)
{
    extern __shared__ char smraw[];
    float* P = (float*)(smraw + SM_P);
    const uint32_t sb = smem_u32(smraw);

    const int tid = threadIdx.x, lane = tid & 31, wid = tid >> 5;
    const int q0  = blockIdx.x * 32;
    const int h   = blockIdx.y;
    const int b   = blockIdx.z;
    const size_t rowbase = (size_t)b*SEQ;
    const int    colQ = h*HD, colK = DM + h*HD, colV = 2*DM + h*HD;

    // ---- load Q tile (hi/lo) into smem ----
    {
        int r = tid >> 3, v = tid & 3;           // 32 rows x 4 vec16 pairs? 64 elems = 8 vecs
        // 32 rows * 8 vecs = 256 slots; tid covers all once
        r = tid >> 3; v = tid & 7;
        const bf16* gh = qkh + (rowbase + q0 + r)*QKVD + colQ + v*8;
        const bf16* gl = qkl + (rowbase + q0 + r)*QKVD + colQ + v*8;
        *(uint4*)(smraw + SM_QH + (r*QPITCH + v*8)*2) = *(const uint4*)gh;
        *(uint4*)(smraw + SM_QL + (r*QPITCH + v*8)*2) = *(const uint4*)gl;
    }

    // ldmatrix lane offsets
    const int aMoff = ((lane >> 3) & 1) * 8 + (lane & 7);
    const int aKby  = (lane >> 4) * 16;
    const int bNoff = lane & 7;
    const int bKby  = ((lane >> 3) & 1) * 16;
    const int nbase = wid * 16;
    const float scale = 0.125f;

    for (int kt = 0; kt < 8; kt++) {
        // load K tile 128x64 hi/lo
#pragma unroll
        for (int i = 0; i < 4; i++) {
            int idx = tid + i*256;               // 0..1023
            int r = idx >> 3, v = idx & 7;
            const bf16* gh = qkh + (rowbase + kt*128 + r)*QKVD + colK + v*8;
            const bf16* gl = qkl + (rowbase + kt*128 + r)*QKVD + colK + v*8;
            *(uint4*)(smraw + SM_KH + (r*QPITCH + v*8)*2) = *(const uint4*)gh;
            *(uint4*)(smraw + SM_KL + (r*QPITCH + v*8)*2) = *(const uint4*)gl;
        }
        __syncthreads();

        float acc[2][2][4];
#pragma unroll
        for (int i = 0; i < 2; i++)
#pragma unroll
            for (int j = 0; j < 2; j++)
#pragma unroll
                for (int c = 0; c < 4; c++) acc[i][j][c] = 0.f;

#pragma unroll
        for (int kk = 0; kk < 4; kk++) {
            uint32_t ah[2][4], al[2][4], bh[2][2], bl[2][2];
#pragma unroll
            for (int mt = 0; mt < 2; mt++) {
                uint32_t aaddr = sb + SM_QH + (mt*16 + aMoff)*QPITCH*2 + kk*32 + aKby;
                ldmx4(ah[mt], aaddr);
                ldmx4(al[mt], aaddr + (SM_QL - SM_QH));
            }
#pragma unroll
            for (int nt = 0; nt < 2; nt++) {
                uint32_t baddr = sb + SM_KH + (nbase + nt*8 + bNoff)*QPITCH*2 + kk*32 + bKby;
                ldmx2(bh[nt], baddr);
                ldmx2(bl[nt], baddr + (SM_KL - SM_KH));
            }
#pragma unroll
            for (int mt = 0; mt < 2; mt++)
#pragma unroll
                for (int nt = 0; nt < 2; nt++) {
                    mma16816(acc[mt][nt], ah[mt], bh[nt]);
                    mma16816(acc[mt][nt], al[mt], bh[nt]);
                    mma16816(acc[mt][nt], ah[mt], bl[nt]);
                }
        }
        // write scores
        const int r0 = lane >> 2, cq = (lane & 3) * 2;
#pragma unroll
        for (int mt = 0; mt < 2; mt++)
#pragma unroll
            for (int nt = 0; nt < 2; nt++) {
                int row = mt*16 + r0;
                int col = kt*128 + nbase + nt*8 + cq;
                P[row*P_LD + col]       = acc[mt][nt][0] * scale;
                P[row*P_LD + col + 1]   = acc[mt][nt][1] * scale;
                P[(row+8)*P_LD + col]   = acc[mt][nt][2] * scale;
                P[(row+8)*P_LD + col+1] = acc[mt][nt][3] * scale;
            }
        __syncthreads();
    }

    // ---- softmax + clip per row (warp per row) ----
    for (int r = wid; r < 32; r += 8) {
        float* row = P + r*P_LD;
        float m = -INFINITY;
        for (int t = lane; t < 1024; t += 32) m = fmaxf(m, row[t]);
#pragma unroll
        for (int o = 16; o; o >>= 1) m = fmaxf(m, __shfl_xor_sync(~0u, m, o));
        float s = 0.f;
        for (int t = lane; t < 1024; t += 32) { float e = __expf(row[t] - m); row[t] = e; s += e; }
#pragma unroll
        for (int o = 16; o; o >>= 1) s += __shfl_xor_sync(~0u, s, o);
        float inv = 1.f / s;
        for (int t = lane; t < 1024; t += 32)
            row[t] = fminf(fmaxf(row[t]*inv, 1e-6f), 1.f);
    }
    __syncthreads();

    // ---- O = P @ V : SIMT f32x2, V fp32 streamed into smem ----
    float* Vs = (float*)(smraw + SM_V);
    const int txo = tid & 15;
    const int tyo = tid >> 4;
    u64 oacc[2][2] = { {0ull,0ull}, {0ull,0ull} };
    for (int vt = 0; vt < 8; vt++) {
        for (int f = tid; f < 128*16; f += 256) {
            int r = f >> 4, c4 = (f & 15) << 2;
            *(float4*)&Vs[r*64 + c4] =
                *(const float4*)(qkv + (rowbase + vt*128 + r)*QKVD + colV + c4);
        }
        __syncthreads();
#pragma unroll 4
        for (int k = 0; k < 128; k++) {
            u64 p0 = pack_dup(P[(tyo*2 + 0)*P_LD + vt*128 + k]);
            u64 p1 = pack_dup(P[(tyo*2 + 1)*P_LD + vt*128 + k]);
#pragma unroll
            for (int j = 0; j < 2; j++) {
                u64 v = *(const u64*)&Vs[k*64 + 2*(txo + 16*j)];
                oacc[0][j] = ffma2(p0, v, oacc[0][j]);
                oacc[1][j] = ffma2(p1, v, oacc[1][j]);
            }
        }
        __syncthreads();
    }
#pragma unroll
    for (int i = 0; i < 2; i++)
#pragma unroll
        for (int j = 0; j < 2; j++) {
            size_t o = (rowbase + q0 + tyo*2 + i)*DM + h*HD + 2*(txo + 16*j);
            split2(lo32(oacc[i][j]), hi32(oacc[i][j]), ctxh + o, ctxl + o);
        }
}

// ---------------- LayerNorm (+ optional split out) ----------------
__global__ __launch_bounds__(256)
void ln_kernel(const float* __restrict__ base, const float* __restrict__ delta,
               const float* __restrict__ g, const float* __restrict__ bta,
               float* __restrict__ out, bf16* __restrict__ oh, bf16* __restrict__ ol)
{
    __shared__ float rowv[DM];
    __shared__ float red[256];
    int row = blockIdx.x, tid = threadIdx.x;
    float local = 0.f;
    for (int d = tid; d < DM; d += 256) {
        float v = base[(size_t)row*DM + d];
        if (delta) v += delta[(size_t)row*DM + d];
        rowv[d] = v; local += v;
    }
    red[tid] = local; __syncthreads();
#pragma unroll
    for (int o = 128; o; o >>= 1) { if (tid < o) red[tid] += red[tid + o]; __syncthreads(); }
    float mean = red[0] * (1.0f/DM);
    __syncthreads();
    local = 0.f;
    for (int d = tid; d < DM; d += 256) { float dv = rowv[d] - mean; local += dv*dv; }
    red[tid] = local; __syncthreads();
#pragma unroll
    for (int o = 128; o; o >>= 1) { if (tid < o) red[tid] += red[tid + o]; __syncthreads(); }
    float inv = rsqrtf(red[0] * (1.0f/DM) + 1e-5f);
    for (int d = tid; d < DM; d += 256) {
        float v = (rowv[d] - mean)*inv*g[d] + bta[d];
        out[(size_t)row*DM + d] = v;
        if (oh) {
            bf16 hv = __float2bfloat16(v);
            oh[(size_t)row*DM + d] = hv;
            ol[(size_t)row*DM + d] = __float2bfloat16(v - __bfloat162float(hv));
        }
    }
}

// ---------------- orchestration ----------------
extern "C" void kernel_launch(void* const* d_in, const int* in_sizes, int n_in,
                              void* d_out, int out_size)
{
    const float* x    = (const float*)d_in[0];
    const float* Wqkv = (const float*)d_in[1];
    const float* bqkv = (const float*)d_in[2];
    const float* Wo   = (const float*)d_in[3];
    const float* bo   = (const float*)d_in[4];
    const float* ln1g = (const float*)d_in[5];
    const float* ln1b = (const float*)d_in[6];
    const float* W1   = (const float*)d_in[7];
    const float* b1   = (const float*)d_in[8];
    const float* W2   = (const float*)d_in[9];
    const float* b2   = (const float*)d_in[10];
    const float* ln2g = (const float*)d_in[11];
    const float* ln2b = (const float*)d_in[12];
    const float* lnfg = (const float*)d_in[13];
    const float* lnfb = (const float*)d_in[14];
    float* out = (float*)d_out;

    float *h, *qkv, *mid;
    bf16 *hh, *hl, *qh, *ql, *ch, *cl, *mh, *ml;
    bf16 *wqkvTh, *wqkvTl, *woTh, *woTl, *w1Th, *w1Tl, *w2Th, *w2Tl;
    cudaGetSymbolAddress((void**)&h,   g_h);
    cudaGetSymbolAddress((void**)&qkv, g_qkv);
    cudaGetSymbolAddress((void**)&mid, g_mid);
    cudaGetSymbolAddress((void**)&hh,  g_hh);
    cudaGetSymbolAddress((void**)&hl,  g_hl);
    cudaGetSymbolAddress((void**)&qh,  g_qh);
    cudaGetSymbolAddress((void**)&ql,  g_ql);
    cudaGetSymbolAddress((void**)&ch,  g_ch);
    cudaGetSymbolAddress((void**)&cl,  g_cl);
    cudaGetSymbolAddress((void**)&mh,  g_mh);
    cudaGetSymbolAddress((void**)&ml,  g_ml);
    cudaGetSymbolAddress((void**)&wqkvTh, g_wqkvT_h);
    cudaGetSymbolAddress((void**)&wqkvTl, g_wqkvT_l);
    cudaGetSymbolAddress((void**)&woTh, g_woT_h);
    cudaGetSymbolAddress((void**)&woTl, g_woT_l);
    cudaGetSymbolAddress((void**)&w1Th, g_w1T_h);
    cudaGetSymbolAddress((void**)&w1Tl, g_w1T_l);
    cudaGetSymbolAddress((void**)&w2Th, g_w2T_h);
    cudaGetSymbolAddress((void**)&w2Tl, g_w2T_l);

    cudaFuncSetAttribute(attn_kernel, cudaFuncAttributeMaxDynamicSharedMemorySize,
                         (int)ATT_SMEM);
    cudaFuncSetAttribute(gemm_bf16_kernel, cudaFuncAttributeMaxDynamicSharedMemorySize,
                         GEMM_SMEM);

    for (int l = 0; l < NL; l++) {
        wsplit_kernel<<<dim3(QKVD/32, DM/32), 256>>>(
            Wqkv + (size_t)l*DM*QKVD, wqkvTh + (size_t)l*QKVD*DM, wqkvTl + (size_t)l*QKVD*DM, DM, QKVD);
        wsplit_kernel<<<dim3(DM/32, DM/32), 256>>>(
            Wo + (size_t)l*DM*DM, woTh + (size_t)l*DM*DM, woTl + (size_t)l*DM*DM, DM, DM);
        wsplit_kernel<<<dim3(FF/32, DM/32), 256>>>(
            W1 + (size_t)l*DM*FF, w1Th + (size_t)l*FF*DM, w1Tl + (size_t)l*FF*DM, DM, FF);
        wsplit_kernel<<<dim3(DM/32, FF/32), 256>>>(
            W2 + (size_t)l*FF*DM, w2Th + (size_t)l*DM*FF, w2Tl + (size_t)l*DM*FF, FF, DM);
    }

    pos_add_kernel<<<MTOT, 256>>>(x, h, hh, hl);

    for (int l = 0; l < NL; l++) {
        // qkv = h @ Wqkv + bqkv  (f32 for V, splits for Q/K)
        gemm_bf16_kernel<<<dim3(QKVD/128, MTOT/128), 256, GEMM_SMEM>>>(
            hh, hl, wqkvTh + (size_t)l*QKVD*DM, wqkvTl + (size_t)l*QKVD*DM,
            bqkv + (size_t)l*QKVD, qkv, qh, ql, MTOT, QKVD, DM, 0);
        // attention -> ctx splits
        attn_kernel<<<dim3(SEQ/32, NH, BATCH), 256, ATT_SMEM>>>(qkv, qh, ql, ch, cl);
        // proj = ctx @ Wo + bo (f32 only)
        gemm_bf16_kernel<<<dim3(DM/128, MTOT/128), 256, GEMM_SMEM>>>(
            ch, cl, woTh + (size_t)l*DM*DM, woTl + (size_t)l*DM*DM,
            bo + (size_t)l*DM, mid, nullptr, nullptr, MTOT, DM, DM, 0);
        // h = LN(h + proj)  (+ splits)
        ln_kernel<<<MTOT, 256>>>(h, mid, ln1g + (size_t)l*DM, ln1b + (size_t)l*DM, h, hh, hl);
        // mid = relu(h @ W1 + b1)  (splits only)
        gemm_bf16_kernel<<<dim3(FF/128, MTOT/128), 256, GEMM_SMEM>>>(
            hh, hl, w1Th + (size_t)l*FF*DM, w1Tl + (size_t)l*FF*DM,
            b1 + (size_t)l*FF, nullptr, mh, ml, MTOT, FF, DM, 1);
        // ffn = mid @ W2 + b2 (f32 only)
        gemm_bf16_kernel<<<dim3(DM/128, MTOT/128), 256, GEMM_SMEM>>>(
            mh, ml, w2Th + (size_t)l*DM*FF, w2Tl + (size_t)l*DM*FF,
            b2 + (size_t)l*DM, mid, nullptr, nullptr, MTOT, DM, FF, 0);
        // h = LN(h + ffn)  (+ splits)
        ln_kernel<<<MTOT, 256>>>(h, mid, ln2g + (size_t)l*DM, ln2b + (size_t)l*DM, h, hh, hl);
    }

    ln_kernel<<<MTOT, 256>>>(h, nullptr, lnfg, lnfb, out, nullptr, nullptr);
}